// round 10
// baseline (speedup 1.0000x reference)
#include <cuda_runtime.h>
#include <cstdint>

#define NT     256
#define PPT    7
#define NTCH   8
#define MAXT   512
#define MAXP   65536
#define NWARP  (NT / 32)
#define PPB    (NT * PPT)   // 1792 priors per block
#define TCHMAX 64
#define FULLM  0xffffffffu

// Scratch — zero-initialized at module load; every call restores zeros itself.
__device__ unsigned long long g_best[MAXT];     // per-truth packed (r_bits<<32 | ~p)
__device__ unsigned long long g_scatter[MAXP];  // per-prior packed ((t+1)<<32 | iou_bits)
__device__ unsigned           g_bto[MAXP];      // per-prior max packed-r (float bits, >=0)
__device__ float              g_sums[3];
__device__ unsigned           g_ctr_main;
__device__ unsigned           g_ctr_red;

__global__ void __launch_bounds__(NT, 2)
k_main(const float2* __restrict__ locs,
       const float*  __restrict__ params,
       const float4* __restrict__ truths,
       int P, int T, int pblocks, int tch, int nblocks) {
    __shared__ float4 s_tr[TCHMAX];
    __shared__ float  s_ta[TCHMAX];
    __shared__ unsigned long long s_best[TCHMAX * NWARP]; // 512 u64 (reused by last block)
    __shared__ float  s_c0[NWARP], s_c2[NWARP];
    __shared__ bool   s_last;

    const int pb  = blockIdx.x % pblocks;
    const int tc  = blockIdx.x / pblocks;
    const int t0  = tc * tch;
    const int t1  = min(min(t0 + tch, T), t0 + TCHMAX);
    const int tid = threadIdx.x;
    const int lane = tid & 31;
    const int wid  = tid >> 5;

    for (int t = t0 + tid; t < t1; t += NT) {
        float4 tb = truths[t];
        s_tr[t - t0] = tb;
        s_ta[t - t0] = (tb.z - tb.x) * (tb.w - tb.y);
    }
    __syncthreads();

    const int pbase = pb * PPB + tid;

    float x0[PPT], y0[PPT], x1[PPT], y1[PPT], ab[PPT], br[PPT];
#pragma unroll
    for (int j = 0; j < PPT; j++) {
        int p = pbase + j * NT;
        float cx, cy, w, h;
        if (p < P) {
            float2 c = locs[p];
            cx = c.x; cy = c.y;
            w = params[3 * p];
            h = params[3 * p + 1];
        } else {
            cx = -1e3f; cy = -1e3f; w = 0.0f; h = 0.0f;
        }
        x0[j] = cx - 0.5f * w;  x1[j] = cx + 0.5f * w;
        y0[j] = cy - 0.5f * h;  y1[j] = cy + 0.5f * h;
        ab[j] = w * h;
        br[j] = 0.0f;           // max packed-r over t
    }

    for (int tt = t0; tt < t1; ++tt) {
        const float4 tb = s_tr[tt - t0];
        const float  ta = s_ta[tt - t0];

        float btr = 0.0f;       // max packed-r over this thread's priors

#pragma unroll
        for (int j = 0; j < PPT; j++) {
            float dx    = fminf(x1[j], tb.z) - fmaxf(x0[j], tb.x);
            float dy    = fminf(y1[j], tb.w) - fmaxf(y0[j], tb.y);
            float inter = fmaxf(dx, 0.0f) * fmaxf(dy, 0.0f);
            float S     = ta + ab[j];               // sum of areas, > 0
            float r     = __fdividef(inter, S);     // MUFU; iou = r/(1-r) monotone
            // pack j into low 3 mantissa bits: argmax becomes a pure max
            float rp = __uint_as_float((__float_as_uint(r) & ~7u) | (unsigned)j);
            br[j] = fmaxf(br[j], rp);
            btr   = fmaxf(btr, rp);
        }

        // warp max (scalar float), then recover the winning lane via ballot
        float mybtr = btr;
#pragma unroll
        for (int off = 16; off > 0; off >>= 1)
            btr = fmaxf(btr, __shfl_xor_sync(FULLM, btr, off));
        unsigned ball = __ballot_sync(FULLM, mybtr == btr);
        if (lane == 0) {
            int lane_w = __ffs(ball) - 1;
            int j_w    = (int)(__float_as_uint(btr) & 7u);
            int p_w    = pb * PPB + wid * 32 + lane_w + j_w * NT;
            s_best[(tt - t0) * NWARP + wid] =
                (((unsigned long long)__float_as_uint(btr)) << 32) |
                (unsigned int)(~p_w);
        }
    }
    __syncthreads();

    // block combine + one global atomic per truth per block
    for (int tt = t0 + tid; tt < t1; tt += NT) {
        unsigned long long m = s_best[(tt - t0) * NWARP];
#pragma unroll
        for (int w = 1; w < NWARP; w++) {
            unsigned long long v = s_best[(tt - t0) * NWARP + w];
            if (v > m) m = v;
        }
        atomicMax(&g_best[tt], m);
    }

    // per-prior best overlap via float-bits atomicMax (values >= 0)
#pragma unroll
    for (int j = 0; j < PPT; j++) {
        int p = pbase + j * NT;
        if (p < P) atomicMax(&g_bto[p], __float_as_uint(br[j]));
    }

    // ---- naturally-last block: scatter + correction terms (no grid spin) ----
    __threadfence();
    if (tid == 0)
        s_last = (atomicAdd(&g_ctr_main, 1u) == (unsigned)(nblocks - 1));
    __syncthreads();
    if (s_last) {
        __threadfence();   // all other blocks' g_best / g_bto atomics visible
        // pass 1: exact iou at each truth's argmax prior; last-t-wins scatter
        for (int t = tid; t < T; t += NT) {
            unsigned long long m = g_best[t];
            unsigned int p = (~((unsigned int)(m & 0xffffffffull))) & (MAXP - 1u);
            g_best[t] = 0ull;                      // restore zeros for next call
            float4 tb = truths[t];
            float2 c  = locs[p];
            float w = params[3 * p];
            float h = params[3 * p + 1];
            float dx = fminf(c.x + 0.5f * w, tb.z) - fmaxf(c.x - 0.5f * w, tb.x);
            float dy = fminf(c.y + 0.5f * h, tb.w) - fmaxf(c.y - 0.5f * h, tb.y);
            float inter = fmaxf(dx, 0.0f) * fmaxf(dy, 0.0f);
            float ta = (tb.z - tb.x) * (tb.w - tb.y);
            float iou = inter / (ta + w * h - inter);   // exact division
            atomicMax(&g_scatter[p],
                (((unsigned long long)(t + 1)) << 32) | __float_as_uint(iou));
            s_best[t] = (((unsigned long long)p) << 32) | (unsigned)(t + 1);
        }
        __threadfence();
        __syncthreads();
        // pass 2: each winning (p, t) contributes a correction to the sums
        float c0 = 0.0f, c2 = 0.0f;
        for (int t = tid; t < T; t += NT) {
            unsigned long long st = s_best[t];
            unsigned int p   = (unsigned int)(st >> 32);
            unsigned int tt1 = (unsigned int)(st & 0xffffffffull);
            unsigned long long sc = g_scatter[p];
            if ((unsigned int)(sc >> 32) == tt1) {   // this t is the last winner for p
                float iou_sc = __uint_as_float((unsigned int)(sc & 0xffffffffull));
                float r      = __uint_as_float(g_bto[p]);
                float bto_b  = __fdividef(r, 1.0f - r);
                float xf_b   = (bto_b > 0.5f) ? 1.0f : 0.0f;
                float a      = params[3 * p + 2];
                float sig    = 1.0f / (1.0f + __expf(-a));
                c0 += sig * (5.0f * iou_sc - xf_b * bto_b);
                c2 += 5.0f - xf_b;
                g_scatter[p] = 0ull;                 // restore zeros for next call
            }
        }
#pragma unroll
        for (int off = 16; off > 0; off >>= 1) {
            c0 += __shfl_xor_sync(FULLM, c0, off);
            c2 += __shfl_xor_sync(FULLM, c2, off);
        }
        if (lane == 0) { s_c0[wid] = c0; s_c2[wid] = c2; }
        __syncthreads();
        if (tid == 0) {
            c0 = 0.0f; c2 = 0.0f;
#pragma unroll
            for (int w = 0; w < NWARP; w++) { c0 += s_c0[w]; c2 += s_c2[w]; }
            atomicAdd(&g_sums[0], c0);
            atomicAdd(&g_sums[2], c2);
            g_ctr_main = 0u;                         // restore for next call
        }
    }
}

// Base sums only: reads g_bto + params (independent loads), no g_scatter.
__global__ void __launch_bounds__(NT)
k_reduce(const float* __restrict__ params,
         float* __restrict__ out, int P, int nblocks) {
    __shared__ float sh0[NWARP], sh1[NWARP], sh2[NWARP];
    __shared__ bool  s_last;
    const int tid  = threadIdx.x;
    const int lane = tid & 31;
    const int wid  = tid >> 5;
    const int p    = blockIdx.x * NT + tid;

    float s0 = 0.0f, s1 = 0.0f, s2 = 0.0f;
    if (p < P) {
        unsigned rb = g_bto[p];                    // load 1
        float a = params[3 * p + 2];               // load 2 (independent)
        g_bto[p] = 0u;                             // restore zeros for next call
        float r   = __uint_as_float(rb);
        float bto = __fdividef(r, 1.0f - r);       // r <= 0.5 always
        float xf  = (bto > 0.5f) ? 1.0f : 0.0f;
        float sig = 1.0f / (1.0f + __expf(-a));
        s0 = sig * xf * bto;
        s1 = sig;          // BETA = 1
        s2 = xf;
    }
#pragma unroll
    for (int off = 16; off > 0; off >>= 1) {
        s0 += __shfl_xor_sync(FULLM, s0, off);
        s1 += __shfl_xor_sync(FULLM, s1, off);
        s2 += __shfl_xor_sync(FULLM, s2, off);
    }
    if (lane == 0) { sh0[wid] = s0; sh1[wid] = s1; sh2[wid] = s2; }
    __syncthreads();
    if (wid == 0) {
        s0 = (lane < NWARP) ? sh0[lane] : 0.0f;
        s1 = (lane < NWARP) ? sh1[lane] : 0.0f;
        s2 = (lane < NWARP) ? sh2[lane] : 0.0f;
#pragma unroll
        for (int off = 4; off > 0; off >>= 1) {
            s0 += __shfl_xor_sync(FULLM, s0, off);
            s1 += __shfl_xor_sync(FULLM, s1, off);
            s2 += __shfl_xor_sync(FULLM, s2, off);
        }
        if (lane == 0) {
            atomicAdd(&g_sums[0], s0);
            atomicAdd(&g_sums[1], s1);
            atomicAdd(&g_sums[2], s2);
        }
    }

    __threadfence();
    if (tid == 0)
        s_last = (atomicAdd(&g_ctr_red, 1u) == (unsigned)(nblocks - 1));
    __syncthreads();
    if (s_last && tid == 0) {
        __threadfence();
        out[0] = (g_sums[0] + g_sums[1]) / g_sums[2];
        g_sums[0] = 0.0f; g_sums[1] = 0.0f; g_sums[2] = 0.0f;
        g_ctr_red = 0u;
    }
}

extern "C" void kernel_launch(void* const* d_in, const int* in_sizes, int n_in,
                              void* d_out, int out_size) {
    const float2* locs   = (const float2*)d_in[0];
    const float*  params = (const float*)d_in[1];
    const float4* truths = (const float4*)d_in[2];
    int P = in_sizes[0] / 2;
    int T = in_sizes[2] / 4;

    int tch     = (T + NTCH - 1) / NTCH;   // 64 for T=512
    int pblocks = (P + PPB - 1) / PPB;     // 37 for P=65536
    int nmain   = pblocks * NTCH;          // 296 = 148 SMs x occ 2 (single wave)

    k_main<<<nmain, NT>>>(locs, params, truths, P, T, pblocks, tch, nmain);
    int nred = (P + NT - 1) / NT;          // 256 blocks, 1 prior/thread
    k_reduce<<<nred, NT>>>(params, (float*)d_out, P, nred);
}